// round 17
// baseline (speedup 1.0000x reference)
#include <cuda_runtime.h>
#include <cuda_bf16.h>

// Contour_to_mask: winding-number mask, 512x512 px, 128 contour points.
// theta = acos(clip(cos,-1+eps,1-eps)) == clip(atan2(|cross|,dot),...); with
// theta = pi/2 -+ v (v>=0) the clamp is exactly v = min(v, pi/2-acos(1-eps)).
// cross_j = tK_j + py*exK_j, dot_j = UK_j + K*py*(py-sy_j), px folded per block.
// 2 px/thread packed f32x2. R17: FOUR independent edge streams per thread
// (QE=16; edges j, j+16, j+32, j+48) -> 4 packed chains for latency hiding.
// rcp batched per stream-pair (A,B) and (C,D): 2 rcp per trip (8 px-edge).
// 256-thread blocks split by edge half (eh = t>>7); partials combined in smem.

#define MSIZE 512
#define NPTS  128
#define EHALF 64
#define QE    16
#define KCONST 100000.0f
#define INV2PI 0.15915494309189535f
#define PI_2F  1.57079632679489662f
#define VMAX   1.5663241903f            /* pi/2 - acos(1 - 1e-5) */

typedef unsigned long long u64;

__device__ __forceinline__ u64 pk2(float lo, float hi) {
    u64 r; asm("mov.b64 %0,{%1,%2};" : "=l"(r) : "f"(lo), "f"(hi)); return r;
}
__device__ __forceinline__ void upk2(u64 v, float& lo, float& hi) {
    asm("mov.b64 {%0,%1},%2;" : "=f"(lo), "=f"(hi) : "l"(v));
}
__device__ __forceinline__ u64 mul2(u64 a, u64 b) {
    u64 r; asm("mul.rn.f32x2 %0,%1,%2;" : "=l"(r) : "l"(a), "l"(b)); return r;
}
__device__ __forceinline__ u64 add2(u64 a, u64 b) {
    u64 r; asm("add.rn.f32x2 %0,%1,%2;" : "=l"(r) : "l"(a), "l"(b)); return r;
}
__device__ __forceinline__ u64 fma2(u64 a, u64 b, u64 c) {
    u64 r; asm("fma.rn.f32x2 %0,%1,%2,%3;" : "=l"(r) : "l"(a), "l"(b), "l"(c)); return r;
}
__device__ __forceinline__ float ftanh(float x) {
    float r; asm("tanh.approx.f32 %0,%1;" : "=f"(r) : "f"(x)); return r;
}
__device__ __forceinline__ float frcp(float x) {
    float r; asm("rcp.approx.f32 %0,%1;" : "=f"(r) : "f"(x)); return r;
}
// +-1.0f carrying the sign of x: one LOP3
__device__ __forceinline__ float sgn1(float x) {
    return __int_as_float(0x3f800000 | (__float_as_int(x) & 0x80000000));
}

struct Chain {
    float cr0, cr1, c0, c1;     // K*cross, K*dot (2 px)
    float a0, a1, b0, b1;       // |cr|, |c|
    float M0, M1, m0, m1, P;    // max, min, M0*M1
};

__device__ __forceinline__ void front_end(
    const ulonglong2 q0, const ulonglong2 q1,
    const u64 pyv, const u64 Kpyv, Chain& ch)
{
    const u64 crv = fma2(pyv, q0.y, q0.x);            // K*cross
    const u64 pys = add2(pyv, q1.y);                  // py - sy
    const u64 dtv = fma2(Kpyv, pys, q1.x);            // K*dot
    upk2(crv, ch.cr0, ch.cr1);
    upk2(dtv, ch.c0, ch.c1);
    ch.a0 = fabsf(ch.cr0); ch.a1 = fabsf(ch.cr1);
    ch.b0 = fabsf(ch.c0);  ch.b1 = fabsf(ch.c1);
    ch.M0 = fmaxf(ch.a0, ch.b0); ch.M1 = fmaxf(ch.a1, ch.b1);
    ch.m0 = fminf(ch.a0, ch.b0); ch.m1 = fminf(ch.a1, ch.b1);
    ch.P  = ch.M0 * ch.M1;
}

// poly + backend for one chain given its reciprocal of P
__device__ __forceinline__ void finish_chain(
    const Chain& ch, float invP,
    const u64 A9, const u64 A7, const u64 A5, const u64 A3, const u64 A1,
    float& sum0, float& sum1)
{
    const u64 rv = mul2(mul2(pk2(ch.m0, ch.m1), pk2(ch.M1, ch.M0)),
                        pk2(invP, invP));
    const u64 r2v = mul2(rv, rv);
    u64 pv = fma2(A9, r2v, A7);
    pv = fma2(pv, r2v, A5);
    pv = fma2(pv, r2v, A3);
    pv = fma2(pv, r2v, A1);
    const u64 av = mul2(pv, rv);
    float al0, al1;
    upk2(av, al0, al1);

    {
        const float h = PI_2F - al0;
        float v = (ch.b0 > ch.a0) ? h : al0;
        v = fminf(v, VMAX);                            // exact reference clamp
        const float th = fmaf(sgn1(ch.c0), -v, PI_2F);
        sum0 = fmaf(ftanh(ch.cr0), th, sum0);          // cr IS K*cross
    }
    {
        const float h = PI_2F - al1;
        float v = (ch.b1 > ch.a1) ? h : al1;
        v = fminf(v, VMAX);
        const float th = fmaf(sgn1(ch.c1), -v, PI_2F);
        sum1 = fmaf(ftanh(ch.cr1), th, sum1);
    }
}

__global__ void __launch_bounds__(256)
contour_mask_kernel(const float* __restrict__ contour, float* __restrict__ out) {
    // flat per-edge constant table, lane-pair duplicated, 16B entries:
    // s[2e]   = (tK, tK, exK, exK)   tK = K*(w - px*ey), exK = K*ex
    // s[2e+1] = (UK, UK, -sy, -sy)   UK = K*(d + px*(px-sx))
    __shared__ float4 s[2 * NPTS];
    __shared__ float2 red[NPTS];            // partial sums from the eh=1 half
    const int t  = threadIdx.x;
    const int p  = t & 127;                 // pixel slot within block
    const int eh = t >> 7;                  // edge half: 0 -> edges 0..63, 1 -> 64..127
    const int row = blockIdx.x >> 1;
    const float px = (float)row * (1.0f / (float)MSIZE);

    // thread t fills table entry for edge e = t>>1, part = t&1
    {
        const int e = t >> 1;
        const float2 c0 = reinterpret_cast<const float2*>(contour)[e];
        const float2 c1 = reinterpret_cast<const float2*>(contour)[(e + 1) & (NPTS - 1)];
        if ((t & 1) == 0) {
            const float w  = fmaf(c0.y, c1.x, -(c0.x * c1.y));
            const float ey = c0.y - c1.y;
            const float tK  = KCONST * fmaf(-px, ey, w);
            const float exK = KCONST * (c0.x - c1.x);
            s[2 * e] = make_float4(tK, tK, exK, exK);
        } else {
            const float d  = fmaf(c0.x, c1.x, c0.y * c1.y);
            const float sx = c0.x + c1.x;
            const float UK = KCONST * fmaf(px, px - sx, d);
            const float nsy = -(c0.y + c1.y);
            s[2 * e + 1] = make_float4(UK, UK, nsy, nsy);
        }
    }
    __syncthreads();

    const int col0 = ((blockIdx.x & 1) << 8) + p;
    const float py0 = (float)col0         * (1.0f / (float)MSIZE);
    const float py1 = (float)(col0 + 128) * (1.0f / (float)MSIZE);
    const u64 pyv  = pk2(py0, py1);
    const u64 Kpyv = pk2(KCONST * py0, KCONST * py1);

    // atan poly, A&S 4.4.47-class (|err| <= 1e-5 rad on [0,1])
    const u64 A9 = pk2( 0.0208351f,  0.0208351f);
    const u64 A7 = pk2(-0.0851330f, -0.0851330f);
    const u64 A5 = pk2( 0.1801410f,  0.1801410f);
    const u64 A3 = pk2(-0.3302995f, -0.3302995f);
    const u64 A1 = pk2( 0.9998660f,  0.9998660f);

    // this half's 64-edge table; FOUR 16-edge streams via bumped pointers
    const ulonglong2* pa = reinterpret_cast<const ulonglong2*>(s + eh * 2 * EHALF);
    const ulonglong2* pb = pa + 2 * QE;
    const ulonglong2* pc = pa + 4 * QE;
    const ulonglong2* pd = pa + 6 * QE;

    float sa0 = 0.0f, sa1 = 0.0f, sb0 = 0.0f, sb1 = 0.0f;
    float sc0 = 0.0f, sc1 = 0.0f, sd0 = 0.0f, sd1 = 0.0f;

#pragma unroll
    for (int j = 0; j < QE; ++j) {
        const ulonglong2 qa0 = pa[0], qa1 = pa[1];
        const ulonglong2 qb0 = pb[0], qb1 = pb[1];
        const ulonglong2 qc0 = pc[0], qc1 = pc[1];
        const ulonglong2 qd0 = pd[0], qd1 = pd[1];
        pa += 2; pb += 2; pc += 2; pd += 2;

        Chain A, B, C, D;
        front_end(qa0, qa1, pyv, Kpyv, A);
        front_end(qb0, qb1, pyv, Kpyv, B);
        front_end(qc0, qc1, pyv, Kpyv, C);
        front_end(qd0, qd1, pyv, Kpyv, D);

        // batched reciprocals per stream pair: 2 MUFU.RCP per trip
        const float invAB = frcp(A.P * B.P);
        const float invCD = frcp(C.P * D.P);
        const float invA = invAB * B.P;
        const float invB = invAB * A.P;
        const float invC = invCD * D.P;
        const float invD = invCD * C.P;

        finish_chain(A, invA, A9, A7, A5, A3, A1, sa0, sa1);
        finish_chain(B, invB, A9, A7, A5, A3, A1, sb0, sb1);
        finish_chain(C, invC, A9, A7, A5, A3, A1, sc0, sc1);
        finish_chain(D, invD, A9, A7, A5, A3, A1, sd0, sd1);
    }

    const float sum0 = (sa0 + sb0) + (sc0 + sd0);
    const float sum1 = (sa1 + sb1) + (sc1 + sd1);

    // in-block reduction of the two edge halves
    if (eh == 1) {
        red[p] = make_float2(sum0, sum1);
    }
    __syncthreads();
    if (eh == 0) {
        const float2 o = red[p];
        const int base = row * MSIZE + col0;
        out[base]       = fminf(fmaxf((sum0 + o.x) * INV2PI, 0.0f), 1.0f);
        out[base + 128] = fminf(fmaxf((sum1 + o.y) * INV2PI, 0.0f), 1.0f);
    }
}

extern "C" void kernel_launch(void* const* d_in, const int* in_sizes, int n_in,
                              void* d_out, int out_size) {
    const float* contour = (const float*)d_in[0];
    float* out = (float*)d_out;
    contour_mask_kernel<<<MSIZE * 2, 256>>>(contour, out);
}